// round 6
// baseline (speedup 1.0000x reference)
#include <cuda_runtime.h>
#include <math.h>

// Problem constants
#define BATCH 1024
#define FDIM  128
#define EDIM  256
#define HEADS 8
#define DHEAD 32
#define MROWS (BATCH * FDIM)   // 131072

// Scratch: Q, K, V projections. __device__ globals — no runtime allocation.
__device__ float g_Q[(size_t)MROWS * EDIM];
__device__ float g_K[(size_t)MROWS * EDIM];
__device__ float g_V[(size_t)MROWS * EDIM];

// ---------------------------------------------------------------------------
// Kernel 1: Y = X @ W for 4 weight matrices.
// X: (131072, 256) row-major.  W: (256, 256) row-major.
// Grid: (8, 1024): blockIdx.x = combo (n-half + matrix) so the 8 CTAs sharing
// one X M-tile are adjacent -> X tile HBM-read once, L2-hit 7x.
// Tiling: BM=128, BN=128, BK=16, 256 threads, 8x8 micro-tile per thread.
// Thread's 8 columns are {tx*4..+3} and {64+tx*4..+3} -> conflict-free Bs reads.
// Register-prefetch double buffering on the k-loop.
// ---------------------------------------------------------------------------
__global__ __launch_bounds__(256)
void proj_kernel(const float* __restrict__ X,
                 const float* __restrict__ Wq, const float* __restrict__ Wk,
                 const float* __restrict__ Wv, const float* __restrict__ Wr,
                 float* __restrict__ Rout)
{
    const int combo = blockIdx.x;            // 0..7
    const int m0 = blockIdx.y * 128;
    const int n0 = (combo & 1) * 128;

    const float* W;
    float* Y;
    switch (combo >> 1) {
        case 0:  W = Wq; Y = g_Q;  break;
        case 1:  W = Wk; Y = g_K;  break;
        case 2:  W = Wv; Y = g_V;  break;
        default: W = Wr; Y = Rout; break;
    }

    __shared__ float As[16][132];   // A tile transposed: As[k][m], padded (+4)
    __shared__ float Bs[16][132];   // B tile: Bs[k][n], padded (+4)

    const int tid = threadIdx.x;
    const int tx  = tid & 15;       // 0..15  (N direction, 2 groups of 4 cols)
    const int ty  = tid >> 4;       // 0..15  (M direction, 8 rows)

    // A-load mapping: 128 rows x 16 cols, float4 per thread, 2 rounds
    const int lrowA = tid >> 2;          // 0..63
    const int lcolA = (tid & 3) * 4;     // 0,4,8,12
    // B-load mapping: 16 rows x 128 cols, float4 per thread, 2 rounds
    const int lrowB = tid >> 5;          // 0..7
    const int lcolB = (tid & 31) * 4;    // 0..124

    float acc[8][8];
    #pragma unroll
    for (int i = 0; i < 8; i++)
        #pragma unroll
        for (int j = 0; j < 8; j++) acc[i][j] = 0.f;

    // Prefetch first k-tile into registers
    float4 pa[2], pb[2];
    #pragma unroll
    for (int r = 0; r < 2; r++) {
        pa[r] = *(const float4*)(X + (size_t)(m0 + lrowA + r * 64) * EDIM + lcolA);
        pb[r] = *(const float4*)(W + (size_t)(lrowB + r * 8) * EDIM + n0 + lcolB);
    }

    for (int k0 = 0; k0 < EDIM; k0 += 16) {
        // Commit staged registers to shared memory
        #pragma unroll
        for (int r = 0; r < 2; r++) {
            const int row = lrowA + r * 64;
            As[lcolA + 0][row] = pa[r].x;
            As[lcolA + 1][row] = pa[r].y;
            As[lcolA + 2][row] = pa[r].z;
            As[lcolA + 3][row] = pa[r].w;
            *(float4*)(&Bs[lrowB + r * 8][lcolB]) = pb[r];
        }
        __syncthreads();

        // Prefetch next k-tile (overlaps with FMA work below)
        if (k0 + 16 < EDIM) {
            #pragma unroll
            for (int r = 0; r < 2; r++) {
                pa[r] = *(const float4*)(X + (size_t)(m0 + lrowA + r * 64) * EDIM + (k0 + 16) + lcolA);
                pb[r] = *(const float4*)(W + (size_t)(k0 + 16 + lrowB + r * 8) * EDIM + n0 + lcolB);
            }
        }

        #pragma unroll
        for (int kk = 0; kk < 16; kk++) {
            float a[8], b[8];
            *(float4*)(a)     = *(const float4*)(&As[kk][ty * 8]);
            *(float4*)(a + 4) = *(const float4*)(&As[kk][ty * 8 + 4]);
            *(float4*)(b)     = *(const float4*)(&Bs[kk][tx * 4]);        // cols tx*4..+3
            *(float4*)(b + 4) = *(const float4*)(&Bs[kk][64 + tx * 4]);   // cols 64+tx*4..+3
            #pragma unroll
            for (int i = 0; i < 8; i++)
                #pragma unroll
                for (int j = 0; j < 8; j++)
                    acc[i][j] = fmaf(a[i], b[j], acc[i][j]);
        }
        __syncthreads();
    }

    // Store 8 rows x (2 groups of 4 cols)
    #pragma unroll
    for (int i = 0; i < 8; i++) {
        const size_t row = (size_t)(m0 + ty * 8 + i);
        #pragma unroll
        for (int g = 0; g < 2; g++) {
            float4 v;
            v.x = acc[i][g * 4 + 0];
            v.y = acc[i][g * 4 + 1];
            v.z = acc[i][g * 4 + 2];
            v.w = acc[i][g * 4 + 3];
            *(float4*)(Y + row * EDIM + n0 + g * 64 + tx * 4) = v;
        }
    }
}

// ---------------------------------------------------------------------------
// Kernel 2: per-(batch, head) attention with online softmax + fused residual/ReLU.
// grid (1024, 8), 128 threads; thread i owns query row i.
// out (= d_out) already contains X @ W_Res from proj_kernel; updated in place.
// K/V smem rows padded to 36 floats: store conflicts 32-way -> 4-way;
// reads are same-address warp broadcasts (conflict-free).
// ---------------------------------------------------------------------------
__global__ __launch_bounds__(128)
void attn_kernel(float* __restrict__ out)
{
    const int b = blockIdx.x;
    const int h = blockIdx.y;
    const int i = threadIdx.x;   // query row 0..127

    __shared__ float Ks[FDIM][36];  // 18 KB (padded)
    __shared__ float Vs[FDIM][36];  // 18 KB (padded)

    const size_t base = (size_t)b * FDIM * EDIM + (size_t)h * DHEAD;

    // Load my Q row into registers; my K/V rows into smem (one 128B line each).
    float q[DHEAD];
    {
        const float* qp = g_Q + base + (size_t)i * EDIM;
        const float* kp = g_K + base + (size_t)i * EDIM;
        const float* vp = g_V + base + (size_t)i * EDIM;
        #pragma unroll
        for (int d4 = 0; d4 < DHEAD / 4; d4++) {
            float4 qv = *(const float4*)(qp + d4 * 4);
            q[d4 * 4 + 0] = qv.x; q[d4 * 4 + 1] = qv.y;
            q[d4 * 4 + 2] = qv.z; q[d4 * 4 + 3] = qv.w;
            *(float4*)(&Ks[i][d4 * 4]) = *(const float4*)(kp + d4 * 4);
            *(float4*)(&Vs[i][d4 * 4]) = *(const float4*)(vp + d4 * 4);
        }
    }
    __syncthreads();

    // Online softmax over keys j, blocked by 8.
    float m   = -INFINITY;
    float sum = 0.f;
    float acc[DHEAD];
    #pragma unroll
    for (int d = 0; d < DHEAD; d++) acc[d] = 0.f;

    #pragma unroll 1
    for (int j0 = 0; j0 < FDIM; j0 += 8) {
        // scores for 8 keys (broadcast float4 smem reads)
        float s[8];
        #pragma unroll
        for (int jj = 0; jj < 8; jj++) s[jj] = 0.f;
        #pragma unroll
        for (int d4 = 0; d4 < DHEAD / 4; d4++) {
            #pragma unroll
            for (int jj = 0; jj < 8; jj++) {
                float4 kv = *(const float4*)(&Ks[j0 + jj][d4 * 4]);
                s[jj] = fmaf(q[d4 * 4 + 0], kv.x,
                        fmaf(q[d4 * 4 + 1], kv.y,
                        fmaf(q[d4 * 4 + 2], kv.z,
                        fmaf(q[d4 * 4 + 3], kv.w, s[jj]))));
            }
        }

        // online-softmax update
        float m_new = m;
        #pragma unroll
        for (int jj = 0; jj < 8; jj++) m_new = fmaxf(m_new, s[jj]);
        const float scale = __expf(m - m_new);   // exp(-inf)=0 on first block
        float p[8];
        float psum = 0.f;
        #pragma unroll
        for (int jj = 0; jj < 8; jj++) {
            p[jj] = __expf(s[jj] - m_new);
            psum += p[jj];
        }
        sum = sum * scale + psum;
        m   = m_new;

        // acc = acc*scale + sum_jj p[jj] * V[j0+jj]
        #pragma unroll
        for (int d4 = 0; d4 < DHEAD / 4; d4++) {
            float ax = acc[d4 * 4 + 0] * scale;
            float ay = acc[d4 * 4 + 1] * scale;
            float az = acc[d4 * 4 + 2] * scale;
            float aw = acc[d4 * 4 + 3] * scale;
            #pragma unroll
            for (int jj = 0; jj < 8; jj++) {
                float4 vv = *(const float4*)(&Vs[j0 + jj][d4 * 4]);
                ax = fmaf(p[jj], vv.x, ax);
                ay = fmaf(p[jj], vv.y, ay);
                az = fmaf(p[jj], vv.z, az);
                aw = fmaf(p[jj], vv.w, aw);
            }
            acc[d4 * 4 + 0] = ax;
            acc[d4 * 4 + 1] = ay;
            acc[d4 * 4 + 2] = az;
            acc[d4 * 4 + 3] = aw;
        }
    }

    // Epilogue: out = relu(attn_out + residual)
    const float inv = 1.0f / sum;
    float* op = out + base + (size_t)i * EDIM;
    #pragma unroll
    for (int d4 = 0; d4 < DHEAD / 4; d4++) {
        float4 r = *(const float4*)(op + d4 * 4);
        float4 o;
        o.x = fmaxf(fmaf(acc[d4 * 4 + 0], inv, r.x), 0.f);
        o.y = fmaxf(fmaf(acc[d4 * 4 + 1], inv, r.y), 0.f);
        o.z = fmaxf(fmaf(acc[d4 * 4 + 2], inv, r.z), 0.f);
        o.w = fmaxf(fmaf(acc[d4 * 4 + 3], inv, r.w), 0.f);
        *(float4*)(op + d4 * 4) = o;
    }
}

// ---------------------------------------------------------------------------
// Inputs (metadata order): [0] inputs (1024,128,256) f32, [1] W_Query (256,256),
// [2] W_key, [3] W_Value, [4] W_Res. Output: (1024,128,256) f32.
// ---------------------------------------------------------------------------
extern "C" void kernel_launch(void* const* d_in, const int* in_sizes, int n_in,
                              void* d_out, int out_size)
{
    const float* X  = (const float*)d_in[0];
    const float* Wq = (const float*)d_in[1];
    const float* Wk = (const float*)d_in[2];
    const float* Wv = (const float*)d_in[3];
    const float* Wr = (const float*)d_in[4];
    float* out = (float*)d_out;

    // 1) Q/K/V/R projections. R lands directly in d_out.
    //    combos fastest so the 8 CTAs per X M-tile are co-resident (L2 reuse).
    dim3 pgrid(8, MROWS / 128, 1);
    proj_kernel<<<pgrid, 256>>>(X, Wq, Wk, Wv, Wr, out);

    // 2) Attention + residual + ReLU (in-place on d_out).
    dim3 agrid(BATCH, HEADS);
    attn_kernel<<<agrid, 128>>>(out);
}

// round 8
// speedup vs baseline: 1.6365x; 1.6365x over previous
#include <cuda_runtime.h>
#include <cuda_fp16.h>
#include <math.h>
#include <stdint.h>

// Problem constants
#define BATCH 1024
#define FDIM  128
#define EDIM  256
#define HEADS 8
#define DHEAD 32
#define MROWS (BATCH * FDIM)   // 131072

// Scratch (no runtime allocation): f32 Q/K/V + fp16 hi/lo operands.
__device__ float g_Q[(size_t)MROWS * EDIM];
__device__ float g_K[(size_t)MROWS * EDIM];
__device__ float g_V[(size_t)MROWS * EDIM];
__device__ __half g_Xhi[(size_t)MROWS * EDIM];
__device__ __half g_Xlo[(size_t)MROWS * EDIM];
__device__ __half g_Wthi[4 * EDIM * EDIM];   // [mat][n][k] (transposed)
__device__ __half g_Wtlo[4 * EDIM * EDIM];

// ---------------------------------------------------------------------------
// Base-ISA helpers (no sm_103a-only instructions: tcgen05 is unavailable
// because the harness compiles at .target sm_103).
// ---------------------------------------------------------------------------
__device__ __forceinline__ uint32_t smem_u32(const void* p) {
    uint32_t a;
    asm("{ .reg .u64 t; cvta.to.shared.u64 t, %1; cvt.u32.u64 %0, t; }" : "=r"(a) : "l"(p));
    return a;
}
__device__ __forceinline__ void cp_async16(uint32_t dst, const void* src) {
    asm volatile("cp.async.cg.shared.global [%0], [%1], 16;" :: "r"(dst), "l"(src));
}
#define CP_COMMIT() asm volatile("cp.async.commit_group;" ::: "memory")
#define CP_WAIT1()  asm volatile("cp.async.wait_group 1;" ::: "memory")
#define CP_WAIT0()  asm volatile("cp.async.wait_group 0;" ::: "memory")

// m16n8k16 fp16 MMA, fp32 accumulate (sm_80+ base instruction -> HMMA)
__device__ __forceinline__ void mma16816(float* d, const uint32_t* a, const uint32_t* b) {
    asm volatile("mma.sync.aligned.m16n8k16.row.col.f32.f16.f16.f32 "
                 "{%0,%1,%2,%3}, {%4,%5,%6,%7}, {%8,%9}, {%0,%1,%2,%3};"
                 : "+f"(d[0]), "+f"(d[1]), "+f"(d[2]), "+f"(d[3])
                 : "r"(a[0]), "r"(a[1]), "r"(a[2]), "r"(a[3]), "r"(b[0]), "r"(b[1]));
}

// ---------------------------------------------------------------------------
// Kernel 0a: split X into fp16 hi/lo.  x = hi + lo + O(2^-22 |x|)
// ---------------------------------------------------------------------------
__global__ __launch_bounds__(256)
void convert_x_kernel(const float* __restrict__ X)
{
    size_t i = ((size_t)blockIdx.x * 256 + threadIdx.x) * 8;   // exact cover
    float4 v0 = *(const float4*)(X + i);
    float4 v1 = *(const float4*)(X + i + 4);
    float x[8] = {v0.x, v0.y, v0.z, v0.w, v1.x, v1.y, v1.z, v1.w};
    union { __half b[8]; uint4 u; } H, L;
    #pragma unroll
    for (int e = 0; e < 8; e++) {
        __half h = __float2half_rn(x[e]);
        H.b[e] = h;
        L.b[e] = __float2half_rn(x[e] - __half2float(h));
    }
    *(uint4*)(g_Xhi + i) = H.u;
    *(uint4*)(g_Xlo + i) = L.u;
}

// ---------------------------------------------------------------------------
// Kernel 0b: split + transpose weights: g_Wt*[mat][n][k] = split(W[k][n])
// ---------------------------------------------------------------------------
__global__ __launch_bounds__(256)
void convert_w_kernel(const float* __restrict__ Wq, const float* __restrict__ Wk,
                      const float* __restrict__ Wv, const float* __restrict__ Wr)
{
    int idx = blockIdx.x * 256 + threadIdx.x;      // 0 .. 262143
    int mat = idx >> 16;
    int rem = idx & 65535;
    int k = rem >> 8;
    int n = rem & 255;
    const float* W = (mat == 0) ? Wq : (mat == 1) ? Wk : (mat == 2) ? Wv : Wr;
    float x = W[k * EDIM + n];
    __half h = __float2half_rn(x);
    int o = mat * 65536 + n * EDIM + k;
    g_Wthi[o] = h;
    g_Wtlo[o] = __float2half_rn(x - __half2float(h));
}

// ---------------------------------------------------------------------------
// Kernel 1: projections via mma.sync fp16 hi/lo (3-term compensation).
// Y[m,n] = sum_k X[m,k] W[k,n] = Xhi*Whi + Xhi*Wlo + Xlo*Whi  (fp32 accum)
// CTA tile M=128 N=128, K in 8 chunks of 32, 2-stage cp.async pipeline.
// 8 warps: warp grid 2(M) x 4(N), warp tile 64x32, 4x4 m16n8k16 frags.
// grid (8, 1024): blockIdx.x = combo (mat*2 + n-half) -> X M-tile L2 reuse.
// ---------------------------------------------------------------------------
#define PADK 40                    // fp16 per smem row (80 B): conflict-free frag loads
#define TILE_H (128 * PADK)        // halves per tile component (10240 B)

__global__ __launch_bounds__(256, 2)
void proj_mma_kernel(float* __restrict__ Rout)
{
    extern __shared__ __align__(16) __half smem[];  // [2 stages][Ahi,Alo,Bhi,Blo][TILE_H]

    const int tid  = threadIdx.x;
    const int lane = tid & 31;
    const int wid  = tid >> 5;
    const int wm   = wid & 1;        // M warp coord (0..1)
    const int wn   = wid >> 1;       // N warp coord (0..3)
    const int g    = lane >> 2;      // group 0..7
    const int t    = lane & 3;       // thread-in-group

    const int combo = blockIdx.x;    // 0..7
    const int mat   = combo >> 1;
    const int n0    = (combo & 1) * 128;
    const int m0    = blockIdx.y * 128;

    float* Y = (mat == 0) ? g_Q : (mat == 1) ? g_K : (mat == 2) ? g_V : Rout;
    const __half* Bhi_src = g_Wthi + (size_t)mat * 65536;
    const __half* Blo_src = g_Wtlo + (size_t)mat * 65536;

    const uint32_t sbase = smem_u32(smem);

    // Issue one K-chunk (32 cols) of all 4 tile components into stage s.
    auto issue = [&](int kc, int s) {
        #pragma unroll
        for (int r = 0; r < 8; r++) {
            const int comp = r >> 1;
            const int idx  = (r & 1) * 256 + tid;   // 0..511
            const int row  = idx >> 2;              // 0..127
            const int seg  = idx & 3;               // 16B segment
            const uint32_t dst = sbase + (uint32_t)((s * 4 + comp) * TILE_H * 2
                                                    + row * (PADK * 2) + seg * 16);
            const __half* src;
            if (comp == 0)      src = g_Xhi   + (size_t)(m0 + row) * EDIM + kc * 32 + seg * 8;
            else if (comp == 1) src = g_Xlo   + (size_t)(m0 + row) * EDIM + kc * 32 + seg * 8;
            else if (comp == 2) src = Bhi_src + (size_t)(n0 + row) * EDIM + kc * 32 + seg * 8;
            else                src = Blo_src + (size_t)(n0 + row) * EDIM + kc * 32 + seg * 8;
            cp_async16(dst, src);
        }
        CP_COMMIT();
    };

    float acc[4][4][4];
    #pragma unroll
    for (int mi = 0; mi < 4; mi++)
        #pragma unroll
        for (int ni = 0; ni < 4; ni++)
            #pragma unroll
            for (int r = 0; r < 4; r++) acc[mi][ni][r] = 0.f;

    issue(0, 0);

    #pragma unroll 1
    for (int kc = 0; kc < 8; kc++) {
        if (kc < 7) { issue(kc + 1, (kc + 1) & 1); CP_WAIT1(); }
        else        { CP_WAIT0(); }
        __syncthreads();

        const __half* Ah = smem + ((kc & 1) * 4 + 0) * TILE_H;
        const __half* Al = smem + ((kc & 1) * 4 + 1) * TILE_H;
        const __half* Bh = smem + ((kc & 1) * 4 + 2) * TILE_H;
        const __half* Bl = smem + ((kc & 1) * 4 + 3) * TILE_H;

        #pragma unroll
        for (int ks = 0; ks < 2; ks++) {         // two k16 steps per chunk
            const int ko = ks * 16;
            // B fragments for all 4 n-frags (hi & lo)
            uint32_t bh[4][2], bl[4][2];
            #pragma unroll
            for (int ni = 0; ni < 4; ni++) {
                const int nr = (wn * 32 + ni * 8 + g) * PADK + ko + 2 * t;
                bh[ni][0] = *(const uint32_t*)(Bh + nr);
                bh[ni][1] = *(const uint32_t*)(Bh + nr + 8);
                bl[ni][0] = *(const uint32_t*)(Bl + nr);
                bl[ni][1] = *(const uint32_t*)(Bl + nr + 8);
            }
            #pragma unroll
            for (int mi = 0; mi < 4; mi++) {
                const int mr0 = (wm * 64 + mi * 16 + g) * PADK + ko + 2 * t;
                const int mr1 = mr0 + 8 * PADK;
                uint32_t ah[4], al[4];
                ah[0] = *(const uint32_t*)(Ah + mr0);
                ah[1] = *(const uint32_t*)(Ah + mr1);
                ah[2] = *(const uint32_t*)(Ah + mr0 + 8);
                ah[3] = *(const uint32_t*)(Ah + mr1 + 8);
                al[0] = *(const uint32_t*)(Al + mr0);
                al[1] = *(const uint32_t*)(Al + mr1);
                al[2] = *(const uint32_t*)(Al + mr0 + 8);
                al[3] = *(const uint32_t*)(Al + mr1 + 8);
                #pragma unroll
                for (int ni = 0; ni < 4; ni++) {
                    mma16816(acc[mi][ni], ah, bh[ni]);   // hi*hi
                    mma16816(acc[mi][ni], ah, bl[ni]);   // hi*lo
                    mma16816(acc[mi][ni], al, bh[ni]);   // lo*hi
                }
            }
        }
        __syncthreads();
    }

    // Epilogue: scatter fp32 fragments to Y (float2 per row-half)
    #pragma unroll
    for (int mi = 0; mi < 4; mi++) {
        const int row = m0 + wm * 64 + mi * 16 + g;
        #pragma unroll
        for (int ni = 0; ni < 4; ni++) {
            const int col = n0 + wn * 32 + ni * 8 + 2 * t;
            float2 v0 = {acc[mi][ni][0], acc[mi][ni][1]};
            float2 v1 = {acc[mi][ni][2], acc[mi][ni][3]};
            *(float2*)(Y + (size_t)row * EDIM + col)       = v0;
            *(float2*)(Y + (size_t)(row + 8) * EDIM + col) = v1;
        }
    }
}

// ---------------------------------------------------------------------------
// Kernel 2: attention, 64 threads per (b,h), 2 query rows per thread.
// Each K/V LDS.128 feeds 8 FMAs (was 4) -> halves the 87.6% L1 bottleneck.
// Online softmax; residual+ReLU fused, in place on d_out.
// ---------------------------------------------------------------------------
__global__ __launch_bounds__(64)
void attn_kernel(float* __restrict__ out)
{
    const int b = blockIdx.x;
    const int h = blockIdx.y;
    const int i = threadIdx.x;        // owns query rows i and i+64

    __shared__ float Ks[FDIM][36];    // padded: store conflicts 32-way -> 4-way
    __shared__ float Vs[FDIM][36];

    const size_t base = (size_t)b * FDIM * EDIM + (size_t)h * DHEAD;

    float q0[DHEAD], q1[DHEAD];
    #pragma unroll
    for (int r = 0; r < 2; r++) {
        const int row = i + r * 64;
        const float* qp = g_Q + base + (size_t)row * EDIM;
        const float* kp = g_K + base + (size_t)row * EDIM;
        const float* vp = g_V + base + (size_t)row * EDIM;
        float* qd = r ? q1 : q0;
        #pragma unroll
        for (int d4 = 0; d4 < DHEAD / 4; d4++) {
            float4 qv = *(const float4*)(qp + d4 * 4);
            qd[d4 * 4 + 0] = qv.x; qd[d4 * 4 + 1] = qv.y;
            qd[d4 * 4 + 2] = qv.z; qd[d4 * 4 + 3] = qv.w;
            *(float4*)(&Ks[row][d4 * 4]) = *(const float4*)(kp + d4 * 4);
            *(float4*)(&Vs[row][d4 * 4]) = *(const float4*)(vp + d4 * 4);
        }
    }
    __syncthreads();

    float m0 = -INFINITY, m1 = -INFINITY;
    float sum0 = 0.f, sum1 = 0.f;
    float acc0[DHEAD], acc1[DHEAD];
    #pragma unroll
    for (int d = 0; d < DHEAD; d++) { acc0[d] = 0.f; acc1[d] = 0.f; }

    #pragma unroll 1
    for (int j0 = 0; j0 < FDIM; j0 += 8) {
        float s0[8], s1[8];
        #pragma unroll
        for (int jj = 0; jj < 8; jj++) { s0[jj] = 0.f; s1[jj] = 0.f; }
        #pragma unroll
        for (int d4 = 0; d4 < DHEAD / 4; d4++) {
            #pragma unroll
            for (int jj = 0; jj < 8; jj++) {
                float4 kv = *(const float4*)(&Ks[j0 + jj][d4 * 4]);
                s0[jj] = fmaf(q0[d4 * 4 + 0], kv.x, fmaf(q0[d4 * 4 + 1], kv.y,
                         fmaf(q0[d4 * 4 + 2], kv.z, fmaf(q0[d4 * 4 + 3], kv.w, s0[jj]))));
                s1[jj] = fmaf(q1[d4 * 4 + 0], kv.x, fmaf(q1[d4 * 4 + 1], kv.y,
                         fmaf(q1[d4 * 4 + 2], kv.z, fmaf(q1[d4 * 4 + 3], kv.w, s1[jj]))));
            }
        }

        float mn0 = m0, mn1 = m1;
        #pragma unroll
        for (int jj = 0; jj < 8; jj++) { mn0 = fmaxf(mn0, s0[jj]); mn1 = fmaxf(mn1, s1[jj]); }
        const float sc0 = __expf(m0 - mn0);
        const float sc1 = __expf(m1 - mn1);
        float ps0 = 0.f, ps1 = 0.f;
        #pragma unroll
        for (int jj = 0; jj < 8; jj++) {
            s0[jj] = __expf(s0[jj] - mn0); ps0 += s0[jj];
            s1[jj] = __expf(s1[jj] - mn1); ps1 += s1[jj];
        }
        sum0 = sum0 * sc0 + ps0;  m0 = mn0;
        sum1 = sum1 * sc1 + ps1;  m1 = mn1;

        #pragma unroll
        for (int d4 = 0; d4 < DHEAD / 4; d4++) {
            float a0x = acc0[d4*4+0]*sc0, a0y = acc0[d4*4+1]*sc0,
                  a0z = acc0[d4*4+2]*sc0, a0w = acc0[d4*4+3]*sc0;
            float a1x = acc1[d4*4+0]*sc1, a1y = acc1[d4*4+1]*sc1,
                  a1z = acc1[d4*4+2]*sc1, a1w = acc1[d4*4+3]*sc1;
            #pragma unroll
            for (int jj = 0; jj < 8; jj++) {
                float4 vv = *(const float4*)(&Vs[j0 + jj][d4 * 4]);
                a0x = fmaf(s0[jj], vv.x, a0x); a0y = fmaf(s0[jj], vv.y, a0y);
                a0z = fmaf(s0[jj], vv.z, a0z); a0w = fmaf(s0[jj], vv.w, a0w);
                a1x = fmaf(s1[jj], vv.x, a1x); a1y = fmaf(s1[jj], vv.y, a1y);
                a1z = fmaf(s1[jj], vv.z, a1z); a1w = fmaf(s1[jj], vv.w, a1w);
            }
            acc0[d4*4+0] = a0x; acc0[d4*4+1] = a0y; acc0[d4*4+2] = a0z; acc0[d4*4+3] = a0w;
            acc1[d4*4+0] = a1x; acc1[d4*4+1] = a1y; acc1[d4*4+2] = a1z; acc1[d4*4+3] = a1w;
        }
    }

    #pragma unroll
    for (int r = 0; r < 2; r++) {
        const int row = i + r * 64;
        const float inv = r ? (1.0f / sum1) : (1.0f / sum0);
        const float* ac = r ? acc1 : acc0;
        float* op = out + base + (size_t)row * EDIM;
        #pragma unroll
        for (int d4 = 0; d4 < DHEAD / 4; d4++) {
            float4 rs = *(const float4*)(op + d4 * 4);
            float4 o;
            o.x = fmaxf(fmaf(ac[d4*4+0], inv, rs.x), 0.f);
            o.y = fmaxf(fmaf(ac[d4*4+1], inv, rs.y), 0.f);
            o.z = fmaxf(fmaf(ac[d4*4+2], inv, rs.z), 0.f);
            o.w = fmaxf(fmaf(ac[d4*4+3], inv, rs.w), 0.f);
            *(float4*)(op + d4 * 4) = o;
        }
    }
}

// ---------------------------------------------------------------------------
// Inputs: [0] inputs (1024,128,256) f32, [1] W_Query, [2] W_key, [3] W_Value,
// [4] W_Res (all 256x256 f32). Output: (1024,128,256) f32.
// ---------------------------------------------------------------------------
extern "C" void kernel_launch(void* const* d_in, const int* in_sizes, int n_in,
                              void* d_out, int out_size)
{
    const float* X  = (const float*)d_in[0];
    const float* Wq = (const float*)d_in[1];
    const float* Wk = (const float*)d_in[2];
    const float* Wv = (const float*)d_in[3];
    const float* Wr = (const float*)d_in[4];
    float* out = (float*)d_out;

    static const int PROJ_SMEM = 2 * 4 * TILE_H * 2;   // 81920 bytes
    cudaFuncSetAttribute(proj_mma_kernel,
                         cudaFuncAttributeMaxDynamicSharedMemorySize, PROJ_SMEM);

    // 0) fp16 hi/lo splits
    convert_x_kernel<<<((size_t)MROWS * EDIM) / (256 * 8), 256>>>(X);
    convert_w_kernel<<<(4 * EDIM * EDIM) / 256, 256>>>(Wq, Wk, Wv, Wr);

    // 1) tensor-core projections; W_Res result lands directly in d_out.
    proj_mma_kernel<<<dim3(8, MROWS / 128), 256, PROJ_SMEM>>>(out);

    // 2) attention + residual + ReLU (in place)
    attn_kernel<<<dim3(BATCH, HEADS), 64>>>(out);
}